// round 17
// baseline (speedup 1.0000x reference)
#include <cuda_runtime.h>
#include <math.h>

#define BB 2
#define N1 384
#define N2 384
#define DD 128
#define HH 128
#define LL 3
#define NF 54

// ---------------- scratch (device globals; no allocation) ----------------
static __device__ float g_h1g[BB*N1*DD];
static __device__ float g_h2g[BB*N2*DD];
static __device__ float g_hX [2*BB*N1*DD];   // ping-pong h
static __device__ float g_hAX[2*BB*N1*DD];   // ping-pong hA
static __device__ float g_P  [BB*N1*N1];
static __device__ float g_PT [BB*N1*N1];
static __device__ float g_m  [BB*N1];
static __device__ float g_iz [BB*N1];
static __device__ float g_p1 [5*BB*N1*HH];
static __device__ float g_p2 [5*BB*N2*HH];
static __device__ float g_WA [LL*DD*DD];
static __device__ float g_bA [LL*DD];
static __device__ float g_pec[288];
static __device__ float g_pev[288];
static __device__ unsigned g_cnt = 0;

__device__ __forceinline__ float sigmoidf_(float x){ return 1.f/(1.f+__expf(-x)); }

// packed f32x2 helpers (sm_100+ PTX): only add/mul/fma exist in f32x2 form.
typedef unsigned long long u64t;
__device__ __forceinline__ u64t px_add(u64t a, u64t b){
    u64t r; asm("add.rn.f32x2 %0, %1, %2;" : "=l"(r) : "l"(a), "l"(b)); return r;
}
__device__ __forceinline__ u64t px_fma(u64t a, u64t b, u64t c){
    u64t r; asm("fma.rn.f32x2 %0, %1, %2, %3;" : "=l"(r) : "l"(a), "l"(b), "l"(c)); return r;
}
__device__ __forceinline__ u64t px_max0(u64t a){
    float x, y;
    asm("mov.b64 {%0, %1}, %2;" : "=f"(x), "=f"(y) : "l"(a));
    x = fmaxf(x, 0.f);
    y = fmaxf(y, 0.f);
    u64t r;
    asm("mov.b64 %0, {%1, %2};" : "=l"(r) : "f"(x), "f"(y));
    return r;
}
__device__ __forceinline__ float px_sum(u64t v){
    float x, y;
    asm("mov.b64 {%0, %1}, %2;" : "=f"(x), "=f"(y) : "l"(v));
    return x + y;
}

// ---------------- fused: WA=W@A, bA=Wb@A  +  node projection ----------------
__global__ __launch_bounds__(128) void k_pre_node(const float* __restrict__ W,
                                                  const float* __restrict__ Wb,
                                                  const float* __restrict__ A,
                                                  const float* __restrict__ h1,
                                                  const float* __restrict__ h2,
                                                  const float* __restrict__ nW){
    int bi = blockIdx.x, d = threadIdx.x;
    if (bi < LL*DD){
        int l = bi / DD, k = bi % DD;
        __shared__ float sw[DD];
        __shared__ float sb[DD];
        sw[d] = W[(l*DD + k)*DD + d];
        if (k == 0) sb[d] = Wb[l*DD + d];
        __syncthreads();
        const float* Al = A + l*DD*DD;
        float acc = 0.f;
        #pragma unroll 8
        for (int m = 0; m < DD; m++) acc += sw[m]*Al[m*DD + d];
        g_WA[(l*DD + k)*DD + d] = acc;
        if (k == 0){
            float bacc = 0.f;
            #pragma unroll 4
            for (int m = 0; m < DD; m++) bacc += sb[m]*Al[m*DD + d];
            g_bA[l*DD + d] = bacc;
        }
    } else {
        int r0 = (bi - LL*DD)*4;
        __shared__ float sx[4][NF];
        bool lig = (r0 < BB*N1);
        const float* src = lig ? (h1 + r0*NF) : (h2 + (r0 - BB*N1)*NF);
        for (int idx = d; idx < 4*NF; idx += 128) ((float*)sx)[idx] = src[idx];
        __syncthreads();
        float acc[4] = {0.f,0.f,0.f,0.f};
        #pragma unroll 2
        for (int k = 0; k < NF; k++){
            float wv = nW[k*DD + d];
            #pragma unroll
            for (int ii = 0; ii < 4; ii++) acc[ii] += sx[ii][k]*wv;
        }
        float* dst = lig ? (g_h1g + r0*DD) : (g_h2g + (r0 - BB*N1)*DD);
        #pragma unroll
        for (int ii = 0; ii < 4; ii++) dst[ii*DD + d] = acc[ii];
    }
}

// ---------------- stage2: gat_h layer0 (192 blocks, 4 rows) + protein pair-proj (240 blocks) ----------------
__global__ __launch_bounds__(128) void k_stage2(const float* __restrict__ gatW,
                                                const float* __restrict__ gatWb,
                                                const float* __restrict__ W1){
    int bi = blockIdx.x, d = threadIdx.x;
    __shared__ float sx[16][DD];
    if (bi < 192){
        int r0 = bi*4;
        #pragma unroll
        for (int ii = 0; ii < 4; ii++) sx[ii][d] = g_h1g[(r0 + ii)*DD + d];
        __syncthreads();
        float wb = gatWb[d], bav = g_bA[d];
        float h[4], ha[4];
        #pragma unroll
        for (int ii = 0; ii < 4; ii++){ h[ii] = wb; ha[ii] = bav; }
        #pragma unroll 8
        for (int k = 0; k < DD; k++){
            float wv  = gatW[k*DD + d];
            float wav = g_WA[k*DD + d];
            #pragma unroll
            for (int ii = 0; ii < 4; ii++){
                h [ii] += sx[ii][k]*wv;
                ha[ii] += sx[ii][k]*wav;
            }
        }
        #pragma unroll
        for (int ii = 0; ii < 4; ii++){
            g_hX [(r0 + ii)*DD + d] = h [ii];
            g_hAX[(r0 + ii)*DD + d] = ha[ii];
        }
    } else {
        int pi = bi - 192;
        int m  = pi / 48;
        int r0 = (pi % 48)*16;
        #pragma unroll
        for (int ii = 0; ii < 16; ii++) sx[ii][d] = g_h2g[(r0 + ii)*DD + d];
        __syncthreads();
        const float* W = W1 + m*2*DD*HH + DD*HH;   // protein half, no bias
        float acc[16];
        #pragma unroll
        for (int ii = 0; ii < 16; ii++) acc[ii] = 0.f;
        #pragma unroll 8
        for (int k = 0; k < DD; k++){
            float wv = W[k*HH + d];
            #pragma unroll
            for (int ii = 0; ii < 16; ii++) acc[ii] = fmaf(sx[ii][k], wv, acc[ii]);
        }
        #pragma unroll
        for (int ii = 0; ii < 16; ii++) g_p2[(m*BB*N2 + r0 + ii)*HH + d] = acc[ii];
    }
}

// ---------------- P = hA @ h^T (and coalesced P^T) : 32x64 tiles, 144 blocks ----------------
__global__ __launch_bounds__(256) void k_e(int cur){
    const float* hb  = g_hX  + cur*BB*N1*DD;
    const float* hab = g_hAX + cur*BB*N1*DD;
    int b = blockIdx.z, j0 = blockIdx.y*32, k0 = blockIdx.x*64;
    __shared__ __align__(16) float sA[64][36];
    __shared__ __align__(16) float sB[64][68];
    int tid = threadIdx.x;
    int tx = tid & 15, ty = tid >> 4;
    float acc[2][4];
    #pragma unroll
    for (int r = 0; r < 2; r++)
        #pragma unroll
        for (int c = 0; c < 4; c++) acc[r][c] = 0.f;
    const float* baseA = hab + (b*N1 + j0)*DD;
    const float* baseB = hb  + (b*N1 + k0)*DD;
    for (int ks = 0; ks < 2; ks++){
        __syncthreads();
        #pragma unroll
        for (int q = 0; q < 2; q++){
            int idx = tid + q*256;
            int row = idx & 31, kq = idx >> 5;
            float4 va = *(const float4*)(baseA + row*DD + ks*64 + kq*4);
            sA[kq*4+0][row] = va.x; sA[kq*4+1][row] = va.y;
            sA[kq*4+2][row] = va.z; sA[kq*4+3][row] = va.w;
        }
        #pragma unroll
        for (int q = 0; q < 4; q++){
            int idx = tid + q*256;
            int row = idx & 63, kq = idx >> 6;
            float4 vb = *(const float4*)(baseB + row*DD + ks*64 + kq*4);
            sB[kq*4+0][row] = vb.x; sB[kq*4+1][row] = vb.y;
            sB[kq*4+2][row] = vb.z; sB[kq*4+3][row] = vb.w;
        }
        __syncthreads();
        #pragma unroll 8
        for (int kk = 0; kk < 64; kk++){
            float2 av = *(const float2*)&sA[kk][ty*2];
            float4 bv = *(const float4*)&sB[kk][tx*4];
            acc[0][0] = fmaf(av.x, bv.x, acc[0][0]);
            acc[0][1] = fmaf(av.x, bv.y, acc[0][1]);
            acc[0][2] = fmaf(av.x, bv.z, acc[0][2]);
            acc[0][3] = fmaf(av.x, bv.w, acc[0][3]);
            acc[1][0] = fmaf(av.y, bv.x, acc[1][0]);
            acc[1][1] = fmaf(av.y, bv.y, acc[1][1]);
            acc[1][2] = fmaf(av.y, bv.z, acc[1][2]);
            acc[1][3] = fmaf(av.y, bv.w, acc[1][3]);
        }
    }
    #pragma unroll
    for (int r = 0; r < 2; r++){
        float4 o = make_float4(acc[r][0], acc[r][1], acc[r][2], acc[r][3]);
        *(float4*)&g_P[(size_t)(b*N1 + j0 + ty*2 + r)*N1 + k0 + tx*4] = o;
    }
    // stage transposed tile into retired sA, then write PT rows coalesced
    __syncthreads();
    float* sT = &sA[0][0];     // 64*36 floats, row stride 36 (16B-aligned rows)
    #pragma unroll
    for (int r = 0; r < 2; r++)
        #pragma unroll
        for (int c = 0; c < 4; c++)
            sT[(tx*4 + c)*36 + ty*2 + r] = acc[r][c];
    __syncthreads();
    #pragma unroll
    for (int q = 0; q < 2; q++){
        int idx = tid + q*256;
        int row = idx >> 3;        // 0..63 (k-tile row)
        int cq  = idx & 7;         // float4 column index 0..7
        float4 v = *(const float4*)&sT[row*36 + cq*4];
        *(float4*)&g_PT[(size_t)(b*N1 + k0 + row)*N1 + j0 + cq*4] = v;
    }
}

// ---------------- column stats via symmetry: 4 rows/block, 192 blocks ----------------
__global__ __launch_bounds__(128) void k_stats(const float* __restrict__ adj){
    int w = threadIdx.x >> 5, lane = threadIdx.x & 31;
    int rg = blockIdx.x*4 + w;                 // global row 0..767
    const float4* pr  = (const float4*)(g_P  + (size_t)rg*N1);
    const float4* ptr = (const float4*)(g_PT + (size_t)rg*N1);
    const float4* ar  = (const float4*)(adj  + (size_t)rg*N1);
    float ev[12];
    float mx = -INFINITY;
    #pragma unroll
    for (int t = 0; t < 3; t++){
        int i4 = lane + t*32;
        float4 a = ar[i4], p = pr[i4], q = ptr[i4];
        float e0 = (a.x > 0.f) ? (p.x + q.x) : -9e15f;
        float e1 = (a.y > 0.f) ? (p.y + q.y) : -9e15f;
        float e2 = (a.z > 0.f) ? (p.z + q.z) : -9e15f;
        float e3 = (a.w > 0.f) ? (p.w + q.w) : -9e15f;
        ev[t*4+0] = e0; ev[t*4+1] = e1; ev[t*4+2] = e2; ev[t*4+3] = e3;
        mx = fmaxf(mx, fmaxf(fmaxf(e0, e1), fmaxf(e2, e3)));
    }
    #pragma unroll
    for (int o = 16; o; o >>= 1) mx = fmaxf(mx, __shfl_xor_sync(0xffffffffu, mx, o));
    float sum = 0.f;
    #pragma unroll
    for (int t = 0; t < 12; t++) sum += __expf(ev[t] - mx);
    #pragma unroll
    for (int o = 16; o; o >>= 1) sum += __shfl_xor_sync(0xffffffffu, sum, o);
    if (lane == 0){
        g_m [rg] = mx;
        g_iz[rg] = 1.f/sum;
    }
}

// ---------------- fused: att on the fly, h'=relu(att@h) smem-tiled, 256 threads row-split ----------------
// tail: either next-layer h/hA, or (l==LL-1) the 5 ligand pair projections
#define FUSE_SMEM (19716*4)
__global__ __launch_bounds__(256) void k_fuse(const float* __restrict__ adj,
                                              const float* __restrict__ gW,
                                              const float* __restrict__ gb,
                                              const float* __restrict__ gatW,
                                              const float* __restrict__ gatWb,
                                              const float* __restrict__ pW1,
                                              const float* __restrict__ pb1,
                                              int l, int has_next){
    extern __shared__ __align__(16) float sm[];
    float* s_h   = sm;                  // [2][64][128]
    float* s_att = sm + 16384;          // [4][384]
    float* s_m   = sm + 16384 + 1536;
    float* s_iz  = s_m + 384;
    float* s_g   = s_iz + 384;          // [4][128]
    float* sx    = s_g + 512;           // [4][128]
    float* s_c   = sx + 512;            // [4]
    int r0 = blockIdx.x*4;
    int b  = r0 / N1;
    int tid = threadIdx.x;
    int d = tid & 127, half = tid >> 7;
    const float* hb = g_hX + (l & 1)*BB*N1*DD;
    const float* hbase = hb + b*N1*DD;
    #pragma unroll
    for (int q = 0; q < 8; q++){
        int idx = tid + q*256;
        int row = idx >> 5, cq = idx & 31;
        *(float4*)&s_h[(size_t)row*DD + cq*4] = *(const float4*)(hbase + row*DD + cq*4);
    }
    for (int idx = tid; idx < N1; idx += 256){
        s_m [idx] = g_m [b*N1 + idx];
        s_iz[idx] = g_iz[b*N1 + idx];
    }
    float xd[2];
    #pragma unroll
    for (int q = 0; q < 2; q++) xd[q] = g_h1g[(r0 + half*2 + q)*DD + d];
    __syncthreads();
    for (int idx4 = tid; idx4 < 4*96; idx4 += 256){
        int ii = idx4 / 96, j4 = idx4 % 96;
        int j  = j4*4;
        float4 a = *(const float4*)(adj  + (size_t)(r0 + ii)*N1 + j);
        float4 p = *(const float4*)(g_P  + (size_t)(r0 + ii)*N1 + j);
        float4 q = *(const float4*)(g_PT + (size_t)(r0 + ii)*N1 + j);
        float4 wv;
        wv.x = (a.x > 0.f) ? __expf(p.x + q.x - s_m[j+0])*s_iz[j+0]*a.x : 0.f;
        wv.y = (a.y > 0.f) ? __expf(p.y + q.y - s_m[j+1])*s_iz[j+1]*a.y : 0.f;
        wv.z = (a.z > 0.f) ? __expf(p.z + q.z - s_m[j+2])*s_iz[j+2]*a.z : 0.f;
        wv.w = (a.w > 0.f) ? __expf(p.w + q.w - s_m[j+3])*s_iz[j+3]*a.w : 0.f;
        *(float4*)&s_att[ii*N1 + j] = wv;
    }
    __syncthreads();
    float hp[2] = {0.f, 0.f};
    const float* awb = s_att + (half*2)*N1;
    for (int t = 0; t < 6; t++){
        if (t < 5){
            const float* src = hbase + (t + 1)*64*DD;
            float* dst = s_h + ((t + 1) & 1)*64*DD;
            #pragma unroll
            for (int q = 0; q < 8; q++){
                int idx = tid + q*256;
                int row = idx >> 5, cq = idx & 31;
                *(float4*)&dst[(size_t)row*DD + cq*4] = *(const float4*)(src + row*DD + cq*4);
            }
        }
        const float* cur = s_h + (t & 1)*64*DD;
        const float* aw  = awb + t*64;
        #pragma unroll 8
        for (int jj = 0; jj < 64; jj++){
            float hv = cur[jj*DD + d];
            hp[0] = fmaf(aw[jj],      hv, hp[0]);
            hp[1] = fmaf(aw[N1 + jj], hv, hp[1]);
        }
        __syncthreads();
    }
    float gw1 = gW[l*2*DD + d], gw2 = gW[l*2*DD + DD + d], gbv = gb[l];
    #pragma unroll
    for (int q = 0; q < 2; q++){
        hp[q] = fmaxf(hp[q], 0.f);
        s_g[(half*2 + q)*DD + d] = fmaf(xd[q], gw1, hp[q]*gw2);
    }
    __syncthreads();
    int w = tid >> 5, lane = tid & 31;
    if (w < 4){
        float s = s_g[w*DD + lane] + s_g[w*DD + lane+32] + s_g[w*DD + lane+64] + s_g[w*DD + lane+96];
        #pragma unroll
        for (int o = 16; o; o >>= 1) s += __shfl_xor_sync(0xffffffffu, s, o);
        if (lane == 0) s_c[w] = sigmoidf_(s + gbv);
    }
    __syncthreads();
    #pragma unroll
    for (int q = 0; q < 2; q++){
        int row = half*2 + q;
        float coeff = s_c[row];
        float v = coeff*xd[q] + (1.f - coeff)*hp[q];
        g_h1g[(r0 + row)*DD + d] = v;
        sx[row*DD + d] = v;
    }
    __syncthreads();
    const float* sxr = sx + (half*2)*DD;
    if (has_next){
        int nl = l + 1;
        const float* W  = gatW + nl*DD*DD;
        const float* WA = g_WA + nl*DD*DD;
        float wb  = gatWb[nl*DD + d];
        float bav = g_bA [nl*DD + d];
        float h[2], ha[2];
        #pragma unroll
        for (int q = 0; q < 2; q++){ h[q] = wb; ha[q] = bav; }
        #pragma unroll 8
        for (int k = 0; k < DD; k++){
            float wv  = W [k*DD + d];
            float wav = WA[k*DD + d];
            #pragma unroll
            for (int q = 0; q < 2; q++){
                h [q] += sxr[q*DD + k]*wv;
                ha[q] += sxr[q*DD + k]*wav;
            }
        }
        float* ho  = g_hX  + (nl & 1)*BB*N1*DD;
        float* hao = g_hAX + (nl & 1)*BB*N1*DD;
        #pragma unroll
        for (int q = 0; q < 2; q++){
            ho [(r0 + half*2 + q)*DD + d] = h [q];
            hao[(r0 + half*2 + q)*DD + d] = ha[q];
        }
    } else {
        // final layer: 5 ligand pair projections for this block's rows
        for (int m = 0; m < 5; m++){
            const float* W = pW1 + m*2*DD*HH;
            float bias = pb1[m*HH + d];
            float a0 = bias, a1 = bias;
            #pragma unroll 8
            for (int k = 0; k < DD; k++){
                float wv = W[k*HH + d];
                a0 = fmaf(sxr[k],      wv, a0);
                a1 = fmaf(sxr[DD + k], wv, a1);
            }
            g_p1[(m*BB*N1 + r0 + half*2 + 0)*HH + d] = a0;
            g_p1[(m*BB*N1 + r0 + half*2 + 1)*HH + d] = a1;
        }
    }
}

// ---------------- pair energies (+ fused finalize in last block) ----------------
__global__ __launch_bounds__(256) void k_pair(const float* __restrict__ dmv,
                                              const float* __restrict__ c1,
                                              const float* __restrict__ c2,
                                              const float* __restrict__ eps,
                                              const float* __restrict__ sig,
                                              const float* __restrict__ val1,
                                              const float* __restrict__ val2,
                                              const float* __restrict__ nmm1,
                                              const float* __restrict__ nmm2,
                                              const float* __restrict__ W2,
                                              const float* __restrict__ b2,
                                              const float* __restrict__ vdwc,
                                              const float* __restrict__ delta_uff,
                                              const float* __restrict__ duff,
                                              const float* __restrict__ iW1,
                                              const float* __restrict__ ib1,
                                              const float* __restrict__ iW2,
                                              const float* __restrict__ ib2,
                                              float* __restrict__ out){
    int bix = blockIdx.x;          // j tile 0..11
    int biy = blockIdx.y;          // i tile 0..23 (32 rows each)
    int r0  = biy*32;
    int b   = r0 / N1;
    int i1  = r0 % N1;
    int j0  = bix*32;
    __shared__ __align__(16) float s_p1[32][132];
    __shared__ __align__(16) float s_p2[32][132];
    __shared__ __align__(16) float s_w2[5][128];
    __shared__ float s_b2v[5];
    __shared__ float s_red[16];
    __shared__ float s_fh[128];
    __shared__ float s_fr[128];
    __shared__ unsigned s_last;
    int tid = threadIdx.x, lane = tid & 31, w = tid >> 5;
    int j  = lane;
    int ia = w*4;
    for (int idx = tid; idx < 5*DD; idx += 256) s_w2[idx/DD][idx%DD] = W2[idx];
    if (tid < 5) s_b2v[tid] = b2[tid];
    float acc[4][5];
    for (int m = 0; m < 5; m++){
        __syncthreads();
        #pragma unroll
        for (int q = 0; q < 4; q++){
            int idx = tid + q*256;
            int row = idx >> 5, q4 = idx & 31;
            float4 v = *(const float4*)(g_p1 + (size_t)(m*BB*N1 + r0 + row)*HH + q4*4);
            *(float4*)&s_p1[row][q4*4] = v;
        }
        #pragma unroll
        for (int q = 0; q < 4; q++){
            int idx = tid + q*256;
            int row = idx >> 5, q4 = idx & 31;
            float4 v = *(const float4*)(g_p2 + (size_t)(m*BB*N2 + b*N2 + j0 + row)*HH + q4*4);
            *(float4*)&s_p2[row][q4*4] = v;
        }
        __syncthreads();
        u64t al[4], ah[4];
        #pragma unroll
        for (int r = 0; r < 4; r++){ al[r] = 0ULL; ah[r] = 0ULL; }
        #pragma unroll
        for (int hv = 0; hv < 32; hv++){
            ulonglong2 w4  = *(const ulonglong2*)&s_w2[m][hv*4];
            ulonglong2 p2v = *(const ulonglong2*)&s_p2[j][hv*4];
            #pragma unroll
            for (int r = 0; r < 4; r++){
                ulonglong2 pa = *(const ulonglong2*)&s_p1[ia + r][hv*4];
                al[r] = px_fma(px_max0(px_add(pa.x, p2v.x)), w4.x, al[r]);
                ah[r] = px_fma(px_max0(px_add(pa.y, p2v.y)), w4.y, ah[r]);
            }
        }
        #pragma unroll
        for (int r = 0; r < 4; r++)
            acc[r][m] = px_sum(al[r]) + px_sum(ah[r]);
    }
    float vdwc2 = vdwc[0]*vdwc[0];
    float ec = 0.f, ev = 0.f;
    int jl = j0 + j;
    float c2v = c2[b*N2 + jl], v2v = val2[b*N2 + jl], n2v = nmm2[b*N2 + jl];
    #pragma unroll
    for (int q = 0; q < 4; q++){
        int il = i1 + ia + q;
        float v0 = acc[q][0] + s_b2v[0];
        float v1 = acc[q][1] + s_b2v[1];
        float v2 = acc[q][2] + s_b2v[2];
        float v3 = acc[q][3] + s_b2v[3];
        float v4 = acc[q][4] + s_b2v[4];
        int pix = (b*N1 + il)*N2 + jl;
        const float* dv = dmv + (size_t)pix*3;
        float dx = dv[0], dy = dv[1], dz = dv[2];
        float dm = sqrtf(dx*dx + dy*dy + dz*dz + 1e-10f);
        if (dm < 0.5f) dm = 1e10f;
        float l2dm = __log2f(dm);
        float cA  = sigmoidf_(v0);
        float cN  = 2.f*sigmoidf_(v1) + 1.f;
        float q12 = c1[b*N1 + il]*c2v;
        float e_c = cA*q12*exp2f(-cN*l2dm);
        e_c *= val1[b*N1 + il]*v2v;
        e_c = fminf(fmaxf(e_c, -100.f), 100.f);
        float vAv = (0.6f*sigmoidf_(v2) + 0.7f)*vdwc2*eps[pix];
        float vBv = tanhf(v3)*0.6f + 0.7f;
        float vNv = 2.f*sigmoidf_(v4) + 5.f;
        float dm0 = sig[pix]*vBv;
        if (dm0 < 1e-4f) dm0 = 1.f;
        float r  = exp2f(vNv*(__log2f(dm0) - l2dm));
        float e_v = vAv*(r*r - 2.f*r);
        e_v *= nmm1[b*N1 + il]*n2v;
        e_v = fminf(e_v, 100.f);
        ec += e_c; ev += e_v;
    }
    #pragma unroll
    for (int o = 16; o; o >>= 1){
        ec += __shfl_xor_sync(0xffffffffu, ec, o);
        ev += __shfl_xor_sync(0xffffffffu, ev, o);
    }
    if (lane == 0){ s_red[w] = ec; s_red[8 + w] = ev; }
    __syncthreads();
    if (tid == 0){
        float tec = 0.f, tev = 0.f;
        #pragma unroll
        for (int qq = 0; qq < 8; qq++){ tec += s_red[qq]; tev += s_red[8 + qq]; }
        g_pec[biy*12 + bix] = tec;
        g_pev[biy*12 + bix] = tev;
        __threadfence();
        unsigned old = atomicAdd(&g_cnt, 1u);
        s_last = (old == 287u) ? 1u : 0u;
    }
    __syncthreads();
    if (!s_last) return;
    if (tid == 0) g_cnt = 0;      // reset for next graph replay
    // -------- finalize (both batches) --------
    for (int bb = 0; bb < BB; bb++){
        if (tid < 128){
            float hs = 0.f;
            for (int i = 0; i < N1; i++) hs += g_h1g[(bb*N1 + i)*DD + tid]*val1[bb*N1 + i];
            s_fh[tid] = hs;
        }
        __syncthreads();
        if (tid < 128){
            float hid = ib1[tid];
            #pragma unroll 4
            for (int k = 0; k < DD; k++) hid += s_fh[k]*iW1[k*HH + tid];
            s_fr[tid] = fmaxf(hid, 0.f)*iW2[tid];
        }
        __syncthreads();
        for (int s = 64; s; s >>= 1){ if (tid < s) s_fr[tid] += s_fr[tid + s]; __syncthreads(); }
        float inter = s_fr[0] + ib2[0];
        __syncthreads();
        if (tid < 128){
            float t = (tid < 128) ? 0.f : 0.f;
            t = 0.f;
            for (int q = tid; q < 144; q += 128) t += g_pec[bb*144 + q];
            s_fr[tid] = t;
        }
        __syncthreads();
        for (int s = 64; s; s >>= 1){ if (tid < s) s_fr[tid] += s_fr[tid + s]; __syncthreads(); }
        float tecs = s_fr[0];
        __syncthreads();
        if (tid < 128){
            float t = 0.f;
            for (int q = tid; q < 144; q += 128) t += g_pev[bb*144 + q];
            s_fr[tid] = t;
        }
        __syncthreads();
        for (int s = 64; s; s >>= 1){ if (tid < s) s_fr[tid] += s_fr[tid + s]; __syncthreads(); }
        if (tid == 0){
            out[bb*4 + 0] = tecs;
            out[bb*4 + 1] = s_fr[0];
            out[bb*4 + 2] = duff[0]*duff[0]*delta_uff[bb];
            out[bb*4 + 3] = inter;
        }
        __syncthreads();
    }
}

// ---------------- launch ----------------
// d_in follows setup_inputs() dict insertion order:
//   0:h1 1:h2 2:adj1 3:dmv 4:charge1 5:charge2 6:vdw_epsilon 7:vdw_sigma
//   8:delta_uff 9:valid1 10:valid2 11:no_metal1 12:no_metal2 13:node_W
//   14:gat_W 15:gat_Wb 16:gat_A 17:gat_gW 18:gat_gb 19:pair_W1 20:pair_b1
//   21:pair_W2 22:pair_b2 23:vdw_coeff 24:duff_coeff 25:int_W1 26:int_b1
//   27:int_W2 28:int_b2
extern "C" void kernel_launch(void* const* d_in, const int* in_sizes, int n_in,
                              void* d_out, int out_size){
    const float* h1        = (const float*)d_in[0];
    const float* h2        = (const float*)d_in[1];
    const float* adj1      = (const float*)d_in[2];
    const float* dmv       = (const float*)d_in[3];
    const float* charge1   = (const float*)d_in[4];
    const float* charge2   = (const float*)d_in[5];
    const float* eps       = (const float*)d_in[6];
    const float* sig       = (const float*)d_in[7];
    const float* delta_uff = (const float*)d_in[8];
    const float* valid1    = (const float*)d_in[9];
    const float* valid2    = (const float*)d_in[10];
    const float* nm1       = (const float*)d_in[11];
    const float* nm2       = (const float*)d_in[12];
    const float* nodeW     = (const float*)d_in[13];
    const float* gatW      = (const float*)d_in[14];
    const float* gatWb     = (const float*)d_in[15];
    const float* gatA      = (const float*)d_in[16];
    const float* gatgW     = (const float*)d_in[17];
    const float* gatgb     = (const float*)d_in[18];
    const float* pW1       = (const float*)d_in[19];
    const float* pb1       = (const float*)d_in[20];
    const float* pW2       = (const float*)d_in[21];
    const float* pb2       = (const float*)d_in[22];
    const float* vdwc      = (const float*)d_in[23];
    const float* duffc     = (const float*)d_in[24];
    const float* iW1       = (const float*)d_in[25];
    const float* ib1       = (const float*)d_in[26];
    const float* iW2       = (const float*)d_in[27];
    const float* ib2       = (const float*)d_in[28];
    float* out = (float*)d_out;

    static int attr_set = 0;
    if (!attr_set){
        cudaFuncSetAttribute(k_fuse, cudaFuncAttributeMaxDynamicSharedMemorySize, FUSE_SMEM);
        attr_set = 1;
    }

    k_pre_node<<<LL*DD + (BB*(N1+N2))/4, 128>>>(gatW, gatWb, gatA, h1, h2, nodeW);
    k_stage2<<<192 + 240, 128>>>(gatW, gatWb, pW1);
    for (int l = 0; l < LL; l++){
        k_e    <<<dim3(N1/64, N1/32, BB), 256>>>(l & 1);
        k_stats<<<BB*N1/4, 128>>>(adj1);
        k_fuse <<<BB*N1/4, 256, FUSE_SMEM>>>(adj1, gatgW, gatgb, gatW, gatWb,
                                             pW1, pb1, l, (l < LL-1) ? 1 : 0);
    }
    k_pair<<<dim3(N2/32, BB*N1/32), 256>>>(dmv, charge1, charge2, eps, sig,
                                           valid1, valid2, nm1, nm2, pW2, pb2, vdwc,
                                           delta_uff, duffc, iW1, ib1, iW2, ib2, out);
}